// round 15
// baseline (speedup 1.0000x reference)
#include <cuda_runtime.h>
#include <cuda_bf16.h>

// Problem: softmask [B=16, K=64, H=240, W=320] fp32.
// out = sqrt( sum over 1024 slices of unbiased variance over H*W=76800 elems )
//
// FINAL — frozen at the machine streaming roofline.
//
// Sweep summary (R2-R14, 12 benches):
//   grid shape 1024/4096, slice splitting ......... neutral (DRAM ~6.25 TB/s)
//   tail: 2-kernel vs last-CTA vs fixed-pt atomic . atomic best (-0.4us)
//   cache hints (ldcs/ldcg) ....................... neutral
//   vector width: LDG.128 vs LDG.256 .............. 256b REGRESSED (-2%)
//   MLP: compiler vs manual 8-deep batching ....... neutral
//   block size: 256 vs 512 ........................ 512 REGRESSED (occ 68%,
//                                                   DRAM 74% -> under plateau)
//   identical-binary replicates (R7/10/13/14) ..... harness 51.20-51.71us,
//                                                   kernel 50.37-50.94us,
//                                                   anti-correlated -> noise
// Conclusion: 6.16-6.32 TB/s is a hard path-independent streaming ceiling
// (documented B300 LTS cap ~6300 B/cyc; TMA == LDG at the cap). Best kernel
// time 50.37us vs 49.8us irreducible transfer -> 1.2% in-kernel overhead.
// Remaining harness delta is graph-launch overhead outside the .cu.
//
// Structure:
//   - one CTA per slice (256 thr), float4 streaming loads (evict-first)
//   - two independent accumulator chains (sum, sumsq)
//   - warp shuffle + smem reduce -> per-slice unbiased variance
//   - cross-slice sum via fixed-point u64 atomicAdd (var * 2^40): integer
//     adds are associative -> bit-deterministic for any arrival order
//   - last CTA (counter) sqrts, writes scalar, resets globals
//     (graph-replay safe; no allocations anywhere)

#define HW        76800            // 240*320
#define HW4       (HW / 4)         // 19200 float4 per slice
#define NSLICES   1024             // 16*64
#define NTHREADS  256
#define FP_SCALE  1099511627776.0  // 2^40

__device__ unsigned long long g_acc   = 0ull;
__device__ unsigned int       g_count = 0;

__global__ __launch_bounds__(NTHREADS)
void loss_concentration_fused(const float4* __restrict__ in,
                              float* __restrict__ out) {
    const int s = blockIdx.x;
    const float4* __restrict__ p = in + (size_t)s * HW4;

    float sum0 = 0.f, sq0 = 0.f;     // two independent chains
    float sum1 = 0.f, sq1 = 0.f;

    // 19200 / 256 = 75 iterations per thread; streaming (evict-first) loads.
    #pragma unroll 5
    for (int i = threadIdx.x; i < HW4; i += NTHREADS) {
        float4 v = __ldcs(&p[i]);
        sum0 += v.x + v.y;
        sum1 += v.z + v.w;
        sq0  += v.x * v.x + v.y * v.y;
        sq1  += v.z * v.z + v.w * v.w;
    }
    float sum = sum0 + sum1;
    float sq  = sq0  + sq1;

    // warp reduce
    #pragma unroll
    for (int off = 16; off > 0; off >>= 1) {
        sum += __shfl_xor_sync(0xffffffffu, sum, off);
        sq  += __shfl_xor_sync(0xffffffffu, sq,  off);
    }

    __shared__ float s_sum[NTHREADS / 32];
    __shared__ float s_sq [NTHREADS / 32];
    const int lane = threadIdx.x & 31;
    const int wid  = threadIdx.x >> 5;
    if (lane == 0) { s_sum[wid] = sum; s_sq[wid] = sq; }
    __syncthreads();

    if (threadIdx.x == 0) {
        float tsum = 0.f, tsq = 0.f;
        #pragma unroll
        for (int w = 0; w < NTHREADS / 32; w++) { tsum += s_sum[w]; tsq += s_sq[w]; }
        // unbiased: (sumsq - sum^2/n) / (n-1)
        float var = (tsq - tsum * tsum * (1.0f / (float)HW))
                    * (1.0f / (float)(HW - 1));
        if (var < 0.f) var = 0.f;                // numerical guard
        // fixed-point contribution: deterministic under any atomic order
        unsigned long long q =
            (unsigned long long)(__double2ll_rn((double)var * FP_SCALE));
        atomicAdd(&g_acc, q);
        __threadfence();                         // acc visible before count
        unsigned old = atomicAdd(&g_count, 1u);
        if (old == NSLICES - 1) {
            unsigned long long total = atomicAdd(&g_acc, 0ull);  // coherent read
            out[0] = sqrtf((float)((double)total * (1.0 / FP_SCALE)));
            g_acc   = 0ull;                      // reset for next graph replay
            g_count = 0;
        }
    }
}

extern "C" void kernel_launch(void* const* d_in, const int* in_sizes, int n_in,
                              void* d_out, int out_size) {
    const float4* in = (const float4*)d_in[0];
    float* out = (float*)d_out;
    loss_concentration_fused<<<NSLICES, NTHREADS>>>(in, out);
}

// round 16
// speedup vs baseline: 1.0094x; 1.0094x over previous
#include <cuda_runtime.h>
#include <cuda_bf16.h>

// Problem: softmask [B=16, K=64, H=240, W=320] fp32.
// out = sqrt( sum over 1024 slices of unbiased variance over H*W=76800 elems )
//
// FINAL — frozen at the machine streaming roofline.
//
// Sweep summary (R2-R15, 13 benches):
//   grid shape 1024/4096, slice splitting ......... neutral (DRAM ~6.25 TB/s)
//   tail: 2-kernel vs last-CTA vs fixed-pt atomic . atomic best (-0.4us)
//   cache hints (ldcs/ldcg) ....................... neutral
//   vector width: LDG.128 vs LDG.256 .............. 256b REGRESSED (-2%)
//   MLP: compiler vs manual 8-deep batching ....... neutral
//   block size: 256 vs 512 ........................ 512 REGRESSED (occ 68%,
//                                                   DRAM 74% -> under plateau)
//   identical-binary replicates (R7/10/13/14/15) .. harness 51.20-51.74us,
//                                                   kernel 50.37-51.10us
//                                                   -> +/-0.5us pure noise
// Conclusion: 6.16-6.32 TB/s is a hard path-independent streaming ceiling
// (documented B300 LTS cap ~6300 B/cyc; TMA == LDG at the cap; no reuse for
// multicast to exploit). Best kernel time 50.37us vs 49.8us irreducible
// transfer -> 1.2% in-kernel overhead. Harness delta is graph-launch cost.
//
// Structure:
//   - one CTA per slice (256 thr), float4 streaming loads (evict-first)
//   - two independent accumulator chains (sum, sumsq)
//   - warp shuffle + smem reduce -> per-slice unbiased variance
//   - cross-slice sum via fixed-point u64 atomicAdd (var * 2^40): integer
//     adds are associative -> bit-deterministic for any arrival order
//   - last CTA (counter) sqrts, writes scalar, resets globals
//     (graph-replay safe; no allocations anywhere)

#define HW        76800            // 240*320
#define HW4       (HW / 4)         // 19200 float4 per slice
#define NSLICES   1024             // 16*64
#define NTHREADS  256
#define FP_SCALE  1099511627776.0  // 2^40

__device__ unsigned long long g_acc   = 0ull;
__device__ unsigned int       g_count = 0;

__global__ __launch_bounds__(NTHREADS)
void loss_concentration_fused(const float4* __restrict__ in,
                              float* __restrict__ out) {
    const int s = blockIdx.x;
    const float4* __restrict__ p = in + (size_t)s * HW4;

    float sum0 = 0.f, sq0 = 0.f;     // two independent chains
    float sum1 = 0.f, sq1 = 0.f;

    // 19200 / 256 = 75 iterations per thread; streaming (evict-first) loads.
    #pragma unroll 5
    for (int i = threadIdx.x; i < HW4; i += NTHREADS) {
        float4 v = __ldcs(&p[i]);
        sum0 += v.x + v.y;
        sum1 += v.z + v.w;
        sq0  += v.x * v.x + v.y * v.y;
        sq1  += v.z * v.z + v.w * v.w;
    }
    float sum = sum0 + sum1;
    float sq  = sq0  + sq1;

    // warp reduce
    #pragma unroll
    for (int off = 16; off > 0; off >>= 1) {
        sum += __shfl_xor_sync(0xffffffffu, sum, off);
        sq  += __shfl_xor_sync(0xffffffffu, sq,  off);
    }

    __shared__ float s_sum[NTHREADS / 32];
    __shared__ float s_sq [NTHREADS / 32];
    const int lane = threadIdx.x & 31;
    const int wid  = threadIdx.x >> 5;
    if (lane == 0) { s_sum[wid] = sum; s_sq[wid] = sq; }
    __syncthreads();

    if (threadIdx.x == 0) {
        float tsum = 0.f, tsq = 0.f;
        #pragma unroll
        for (int w = 0; w < NTHREADS / 32; w++) { tsum += s_sum[w]; tsq += s_sq[w]; }
        // unbiased: (sumsq - sum^2/n) / (n-1)
        float var = (tsq - tsum * tsum * (1.0f / (float)HW))
                    * (1.0f / (float)(HW - 1));
        if (var < 0.f) var = 0.f;                // numerical guard
        // fixed-point contribution: deterministic under any atomic order
        unsigned long long q =
            (unsigned long long)(__double2ll_rn((double)var * FP_SCALE));
        atomicAdd(&g_acc, q);
        __threadfence();                         // acc visible before count
        unsigned old = atomicAdd(&g_count, 1u);
        if (old == NSLICES - 1) {
            unsigned long long total = atomicAdd(&g_acc, 0ull);  // coherent read
            out[0] = sqrtf((float)((double)total * (1.0 / FP_SCALE)));
            g_acc   = 0ull;                      // reset for next graph replay
            g_count = 0;
        }
    }
}

extern "C" void kernel_launch(void* const* d_in, const int* in_sizes, int n_in,
                              void* d_out, int out_size) {
    const float4* in = (const float4*)d_in[0];
    float* out = (float*)d_out;
    loss_concentration_fused<<<NSLICES, NTHREADS>>>(in, out);
}